// round 12
// baseline (speedup 1.0000x reference)
#include <cuda_runtime.h>
#include <stdint.h>

// ---------------------------------------------------------------------------
// AUAvULoss. Phase 1: double-buffered cp.async tiles, row-per-thread softmax
// stats + tanh/weights precompute (13-bit fixed point, packed u32).
// Phase 2: atomic-free binning via warp broadcast loop into register u64
// accumulators; integer global reduction (fully deterministic).
// N = 1<<20 rows, C = 100 classes.
// ---------------------------------------------------------------------------

#define NMAX (1 << 20)
#define NTH 21
#define EPSV 1e-10
#define SUB_ROWS 128
#define ROW_F4 25                     // 100 floats = 25 float4 per row
#define SUB_F4 (SUB_ROWS * ROW_F4)    // 3200 float4 = 51,200 B per buffer
#define L2E 1.4426950408889634f
#define WSCALE 8191.0f

__device__ float2             g_ec[NMAX];           // {entropy, packed u32 bits}
__device__ int                g_umin_bits = 0x7f7fffff;
__device__ int                g_umax_bits = 0;
__device__ unsigned long long g_h64[2][2][NTH];     // [ro][c/u][bin], zero-init
__device__ unsigned           g_done;               // zero-init

// ---------------------------------------------------------------------------
__device__ __forceinline__ unsigned smem_u32(const void* p) {
    unsigned a;
    asm("{ .reg .u64 t; cvta.to.shared.u64 t, %1; cvt.u32.u64 %0, t; }"
        : "=r"(a) : "l"(p));
    return a;
}
__device__ __forceinline__ void cp16(unsigned s, const void* g) {
    asm volatile("cp.async.cg.shared.global [%0], [%1], 16;" :: "r"(s), "l"(g));
}

// ---------------------------------------------------------------------------
// Phase 1: grid-stride over 128-row sub-tiles with 2-buffer cp.async pipeline.
// All 256 threads load; threads 0..127 each own one full row from smem.
__global__ void __launch_bounds__(256) k_phase1(
    const float4* __restrict__ l4, const int* __restrict__ labels,
    int N, int nSub)
{
    extern __shared__ float4 sbuf[];   // 2 * SUB_F4 float4 = 102,400 B
    const int tid = threadIdx.x;
    const unsigned sb = smem_u32(sbuf);
    const float POS = __int_as_float(0x7f800000);

    float emin = POS, emax = 0.f;

    // prologue: load first sub-tile into buffer 0
    {
        int s = blockIdx.x;
        if (s < nSub) {
            const float4* src = l4 + (size_t)s * SUB_F4;
            int lim = min(SUB_F4, (N - s * SUB_ROWS) * ROW_F4);
            #pragma unroll
            for (int k = 0; k < 13; k++) {
                int idx = tid + k * 256;
                if (idx < lim) cp16(sb + idx * 16, src + idx);
            }
        }
        asm volatile("cp.async.commit_group;");
    }

    int buf = 0;
    for (int s = blockIdx.x; s < nSub; s += gridDim.x) {
        int sn = s + gridDim.x;
        if (sn < nSub) {   // prefetch next sub-tile into other buffer
            const float4* src = l4 + (size_t)sn * SUB_F4;
            unsigned dst = sb + (buf ^ 1) * (SUB_F4 * 16);
            int lim = min(SUB_F4, (N - sn * SUB_ROWS) * ROW_F4);
            #pragma unroll
            for (int k = 0; k < 13; k++) {
                int idx = tid + k * 256;
                if (idx < lim) cp16(dst + idx * 16, src + idx);
            }
        }
        asm volatile("cp.async.commit_group;");
        asm volatile("cp.async.wait_group 1;");   // current sub-tile ready
        __syncthreads();

        int grow = s * SUB_ROWS + tid;
        if (tid < SUB_ROWS && grow < N) {
            const float4* r = sbuf + buf * SUB_F4 + tid * ROW_F4;
            float m0 = -POS, m1 = -POS;
            float S0 = 0.f, S1 = 0.f, U0 = 0.f, U1 = 0.f;
            #pragma unroll
            for (int k = 0; k < ROW_F4; k++) {
                float4 v = r[k];
                float e0 = exp2f(v.x * L2E), e1 = exp2f(v.y * L2E);
                float e2 = exp2f(v.z * L2E), e3 = exp2f(v.w * L2E);
                m0 = fmaxf(m0, fmaxf(v.x, v.y));
                m1 = fmaxf(m1, fmaxf(v.z, v.w));
                S0 += e0 + e1;
                S1 += e2 + e3;
                U0 = fmaf(e0, v.x, fmaf(e1, v.y, U0));
                U1 = fmaf(e2, v.z, fmaf(e3, v.w, U1));
            }
            float m = fmaxf(m0, m1);
            float S = S0 + S1, U = U0 + U1;

            int   lab = labels[grow];
            float xl  = ((const float*)r)[lab];

            float rcpS = __frcp_rn(S);
            float ent  = __logf(S) - U * rcpS;        // entropy (>0)
            float conf = exp2f(m * L2E) * rcpS;       // max prob

            // tanh(ent) = 1 - 2/(e^{2*ent}+1), ent >= 0
            float e2t = exp2f(ent * (2.f * L2E));
            float tu  = 1.f - 2.f * __frcp_rn(e2t + 1.f);

            bool acc = (xl == m);
            float a  = acc ? conf : (1.f - conf);
            unsigned wc13 = (unsigned)__float2int_rn(a * (1.f - tu) * WSCALE);
            unsigned wu13 = (unsigned)__float2int_rn(a * tu * WSCALE);
            unsigned p = (wu13 << 19) | (wc13 << 6) | (acc ? 0u : 32u);

            g_ec[grow] = make_float2(ent, __uint_as_float(p));
            emin = fminf(emin, ent);
            emax = fmaxf(emax, ent);
        }
        __syncthreads();   // buffer may be reloaded next iteration
        buf ^= 1;
    }

    // block reduce entropy min/max (int-bit ordering valid: entropy > 0)
    __shared__ int smin, smax;
    if (tid == 0) { smin = 0x7f7fffff; smax = 0; }
    __syncthreads();
    if (emin < POS) {
        atomicMin(&smin, __float_as_int(emin));
        atomicMax(&smax, __float_as_int(emax));
    }
    __syncthreads();
    if (tid == 0) {
        atomicMin(&g_umin_bits, smin);
        atomicMax(&g_umax_bits, smax);
    }
}

// ---------------------------------------------------------------------------
// Phase 2: per-warp register histogram via broadcast loop (no atomics in the
// hot path), integer global flush. Last block: AvU -> AUC -> loss + reset.
__global__ void __launch_bounds__(256) k_phase2(int N, float* out) {
    const unsigned FULL = 0xFFFFFFFFu;
    const int lane  = threadIdx.x & 31;
    const int gwarp = (blockIdx.x * blockDim.x + threadIdx.x) >> 5;
    const int nwarp = (gridDim.x * blockDim.x) >> 5;
    __shared__ bool isLast;

    const float umin  = __int_as_float(g_umin_bits);
    const float range = __int_as_float(g_umax_bits) - umin;
    const float inv   = 20.f / range;

    unsigned long long accA = 0ull, accB = 0ull;  // lane's bin: {wc lo32, wu hi32}

    for (int base = gwarp * 32; base < N; base += nwarp * 32) {
        int i = base + lane;
        unsigned p = 31u;            // oob sentinel: bin 31 (ignored), weights 0
        if (i < N) {
            float2 ec = g_ec[i];
            float ent = ec.x;
            unsigned q = __float_as_uint(ec.y);

            // bin = #{t : th(t) < ent}; direct estimate + boundary fixup
            int b = (int)((ent - umin) * inv);
            b = max(0, min(20, b));
            float thb = fmaf((float)b * 0.05f, range, umin);
            if (ent > thb) b++;
            else if (b > 0 && ent <= fmaf((float)(b - 1) * 0.05f, range, umin)) b--;
            if (b > 20) b = 20;
            p = q | (unsigned)b;
        }
        #pragma unroll
        for (int r = 0; r < 32; r++) {
            unsigned v = __shfl_sync(FULL, p, r);
            if ((v & 31u) == (unsigned)lane) {
                unsigned long long add =
                    ((unsigned long long)(v >> 19) << 32) | ((v >> 6) & 0x1FFFu);
                if (v & 32u) accB += add; else accA += add;
            }
        }
    }

    // flush per-warp accumulators (integer RED -> deterministic)
    if (lane < NTH) {
        atomicAdd(&g_h64[0][0][lane], accA & 0xFFFFFFFFull);
        atomicAdd(&g_h64[0][1][lane], accA >> 32);
        atomicAdd(&g_h64[1][0][lane], accB & 0xFFFFFFFFull);
        atomicAdd(&g_h64[1][1][lane], accB >> 32);
    }
    __syncthreads();

    // last-block epilogue
    if (threadIdx.x == 0) {
        __threadfence();
        unsigned done = atomicAdd(&g_done, 1u);
        isLast = (done == gridDim.x - 1);
    }
    __syncthreads();
    if (isLast && threadIdx.x < 32) {
        const double SC = 1.0 / (double)WSCALE;
        double cac = 0, cau = 0, cic = 0, ciu = 0, au_all = 0, iu_all = 0;
        for (int t = 0; t < NTH; t++) {
            double h0 = (double)g_h64[0][0][t] * SC;  // ac
            double h1 = (double)g_h64[0][1][t] * SC;  // au
            double h2 = (double)g_h64[1][0][t] * SC;  // ic
            double h3 = (double)g_h64[1][1][t] * SC;  // iu
            au_all += h1; iu_all += h3;
            if (t <= lane) { cac += h0; cau += h1; cic += h2; ciu += h3; }
        }
        double avu = 0.0;
        if (lane < NTH) {
            double n_au = au_all - cau, n_iu = iu_all - ciu;
            avu = (cac + n_iu) / (cac + n_au + cic + n_iu + EPSV);
        }
        double nxt = __shfl_down_sync(FULL, avu, 1);
        double seg = 0.0;
        if (lane < NTH - 1) {
            float dt = (float)(lane + 1) * 0.05f - (float)lane * 0.05f;
            seg = 0.5 * (avu + nxt) * (double)dt;
        }
        #pragma unroll
        for (int off = 16; off; off >>= 1)
            seg += __shfl_xor_sync(FULL, seg, off);
        if (lane == 0) {
            out[0] = (float)(-log(seg + EPSV));  // avu_loss
            out[1] = (float)seg;                 // auc_avu
        }
        __syncwarp();
        // reset global reduction state for the next graph replay
        for (int t = lane; t < 2 * 2 * NTH; t += 32)
            ((unsigned long long*)g_h64)[t] = 0ull;
        if (lane == 0) {
            g_umin_bits = 0x7f7fffff;
            g_umax_bits = 0;
            g_done = 0u;
        }
    }
}

// ---------------------------------------------------------------------------
extern "C" void kernel_launch(void* const* d_in, const int* in_sizes, int n_in,
                              void* d_out, int out_size) {
    const float* logits = (const float*)d_in[0];
    const int*   labels = (const int*)d_in[1];
    int N = in_sizes[1];  // labels count = rows
    if (N > NMAX) N = NMAX;
    int nSub = (N + SUB_ROWS - 1) / SUB_ROWS;

    static int smemSet = 0;
    if (!smemSet) {
        cudaFuncSetAttribute(k_phase1, cudaFuncAttributeMaxDynamicSharedMemorySize,
                             2 * SUB_F4 * 16);
        smemSet = 1;
    }

    // 296 blocks = 2 resident/SM (2 x 100KB smem), double-buffered pipeline
    k_phase1<<<296, 256, 2 * SUB_F4 * 16>>>(
        (const float4*)logits, labels, N, nSub);
    k_phase2<<<592, 256>>>(N, (float*)d_out);
}

// round 13
// speedup vs baseline: 1.3195x; 1.3195x over previous
#include <cuda_runtime.h>
#include <stdint.h>

// ---------------------------------------------------------------------------
// AUAvULoss. Phase 1: double-buffered cp.async tiles, row-per-thread softmax
// stats + tanh/weight precompute (16-bit fixed point; accurate flag in the
// sign bit of entropy). Phase 2: warp-private u64 smem histograms, ONE
// integer ATOMS.64 per row, integer global flush (deterministic).
// N = 1<<20 rows, C = 100 classes.
// ---------------------------------------------------------------------------

#define NMAX (1 << 20)
#define NTH 21
#define EPSV 1e-10
#define SUB_ROWS 128
#define ROW_F4 25                     // 100 floats = 25 float4 per row
#define SUB_F4 (SUB_ROWS * ROW_F4)    // 3200 float4 = 51,200 B per buffer
#define L2E 1.4426950408889634f
#define WSCALE 65535.0f

__device__ float2             g_ec[NMAX];        // {+/-entropy (sign=!acc), wc16|wu16<<16}
__device__ int                g_umin_bits = 0x7f7fffff;
__device__ int                g_umax_bits = 0;
__device__ unsigned long long g_h64[2][2][NTH];  // [acc][wc/wu][bin], zero-init
__device__ unsigned           g_done;            // zero-init

// ---------------------------------------------------------------------------
__device__ __forceinline__ unsigned smem_u32(const void* p) {
    unsigned a;
    asm("{ .reg .u64 t; cvta.to.shared.u64 t, %1; cvt.u32.u64 %0, t; }"
        : "=r"(a) : "l"(p));
    return a;
}
__device__ __forceinline__ void cp16(unsigned s, const void* g) {
    asm volatile("cp.async.cg.shared.global [%0], [%1], 16;" :: "r"(s), "l"(g));
}

// ---------------------------------------------------------------------------
// Phase 1: grid-stride over 128-row sub-tiles with 2-buffer cp.async pipeline.
// All 256 threads load; threads 0..127 each own one full row from smem.
__global__ void __launch_bounds__(256) k_phase1(
    const float4* __restrict__ l4, const int* __restrict__ labels,
    int N, int nSub)
{
    extern __shared__ float4 sbuf[];   // 2 * SUB_F4 float4 = 102,400 B
    const int tid = threadIdx.x;
    const unsigned sb = smem_u32(sbuf);
    const float POS = __int_as_float(0x7f800000);

    float emin = POS, emax = 0.f;

    // prologue: load first sub-tile into buffer 0
    {
        int s = blockIdx.x;
        if (s < nSub) {
            const float4* src = l4 + (size_t)s * SUB_F4;
            int lim = min(SUB_F4, (N - s * SUB_ROWS) * ROW_F4);
            #pragma unroll
            for (int k = 0; k < 13; k++) {
                int idx = tid + k * 256;
                if (idx < lim) cp16(sb + idx * 16, src + idx);
            }
        }
        asm volatile("cp.async.commit_group;");
    }

    int buf = 0;
    for (int s = blockIdx.x; s < nSub; s += gridDim.x) {
        int sn = s + gridDim.x;
        if (sn < nSub) {   // prefetch next sub-tile into other buffer
            const float4* src = l4 + (size_t)sn * SUB_F4;
            unsigned dst = sb + (buf ^ 1) * (SUB_F4 * 16);
            int lim = min(SUB_F4, (N - sn * SUB_ROWS) * ROW_F4);
            #pragma unroll
            for (int k = 0; k < 13; k++) {
                int idx = tid + k * 256;
                if (idx < lim) cp16(dst + idx * 16, src + idx);
            }
        }
        asm volatile("cp.async.commit_group;");
        asm volatile("cp.async.wait_group 1;");   // current sub-tile ready
        __syncthreads();

        int grow = s * SUB_ROWS + tid;
        if (tid < SUB_ROWS && grow < N) {
            const float4* r = sbuf + buf * SUB_F4 + tid * ROW_F4;
            float m0 = -POS, m1 = -POS;
            float S0 = 0.f, S1 = 0.f, U0 = 0.f, U1 = 0.f;
            #pragma unroll
            for (int k = 0; k < ROW_F4; k++) {
                float4 v = r[k];
                float e0 = exp2f(v.x * L2E), e1 = exp2f(v.y * L2E);
                float e2 = exp2f(v.z * L2E), e3 = exp2f(v.w * L2E);
                m0 = fmaxf(m0, fmaxf(v.x, v.y));
                m1 = fmaxf(m1, fmaxf(v.z, v.w));
                S0 += e0 + e1;
                S1 += e2 + e3;
                U0 = fmaf(e0, v.x, fmaf(e1, v.y, U0));
                U1 = fmaf(e2, v.z, fmaf(e3, v.w, U1));
            }
            float m = fmaxf(m0, m1);
            float S = S0 + S1, U = U0 + U1;

            int   lab = labels[grow];
            float xl  = ((const float*)r)[lab];

            float rcpS = __frcp_rn(S);
            float ent  = __logf(S) - U * rcpS;        // entropy (>0)
            float conf = exp2f(m * L2E) * rcpS;       // max prob

            // tanh(ent) = 1 - 2/(e^{2*ent}+1), ent >= 0
            float e2t = exp2f(ent * (2.f * L2E));
            float tu  = 1.f - 2.f * __frcp_rn(e2t + 1.f);

            bool acc = (xl == m);
            float a  = acc ? conf : (1.f - conf);
            unsigned wc = (unsigned)__float2int_rn(a * (1.f - tu) * WSCALE);
            unsigned wu = (unsigned)__float2int_rn(a * tu * WSCALE);

            float es = acc ? ent : __uint_as_float(__float_as_uint(ent) | 0x80000000u);
            g_ec[grow] = make_float2(es, __uint_as_float(wc | (wu << 16)));
            emin = fminf(emin, ent);
            emax = fmaxf(emax, ent);
        }
        __syncthreads();   // buffer may be reloaded next iteration
        buf ^= 1;
    }

    // block reduce entropy min/max (int-bit ordering valid: entropy > 0)
    __shared__ int smin, smax;
    if (tid == 0) { smin = 0x7f7fffff; smax = 0; }
    __syncthreads();
    if (emin < POS) {
        atomicMin(&smin, __float_as_int(emin));
        atomicMax(&smax, __float_as_int(emax));
    }
    __syncthreads();
    if (tid == 0) {
        atomicMin(&g_umin_bits, smin);
        atomicMax(&g_umax_bits, smax);
    }
}

// ---------------------------------------------------------------------------
// Phase 2: warp-private smem u64 histograms (wc lo32 / wu hi32, carry-free),
// one ATOMS.64 per row. Block-combine -> split-field global integer atomics.
// Last block: AvU -> trapezoid AUC -> loss, then resets global state.
__global__ void __launch_bounds__(256) k_phase2(int N, float* out) {
    const unsigned FULL = 0xFFFFFFFFu;
    const int lane = threadIdx.x & 31;
    const int wid  = threadIdx.x >> 5;
    __shared__ unsigned long long sh[8][2][NTH];   // [warp][acc][bin]
    __shared__ bool isLast;

    for (int t = threadIdx.x; t < 8 * 2 * NTH; t += blockDim.x)
        ((unsigned long long*)sh)[t] = 0ull;
    __syncthreads();

    const float umin  = __int_as_float(g_umin_bits);
    const float range = __int_as_float(g_umax_bits) - umin;
    const float inv   = 20.f / range;

    for (int i = blockIdx.x * blockDim.x + threadIdx.x; i < N;
         i += gridDim.x * blockDim.x) {
        float2 ec = g_ec[i];
        unsigned eb = __float_as_uint(ec.x);
        int accIdx = (int)(eb >> 31);                    // 0 = accurate
        float ent = __uint_as_float(eb & 0x7FFFFFFFu);

        // bin = #{t : th(t) < ent}; direct estimate + boundary fixup
        int b = (int)((ent - umin) * inv);
        b = max(0, min(20, b));
        float thb = fmaf((float)b * 0.05f, range, umin);
        if (ent > thb) b++;
        else if (b > 0 && ent <= fmaf((float)(b - 1) * 0.05f, range, umin)) b--;
        if (b > 20) b = 20;

        unsigned q = __float_as_uint(ec.y);
        unsigned long long add =
            ((unsigned long long)(q >> 16) << 32) | (q & 0xFFFFu);
        atomicAdd(&sh[wid][accIdx][b], add);
    }
    __syncthreads();

    // block-combine 8 warp copies, flush split fields to global (integer)
    for (int t = threadIdx.x; t < 2 * NTH; t += blockDim.x) {
        int a = t / NTH, b = t % NTH;
        unsigned long long s = 0ull;
        #pragma unroll
        for (int w = 0; w < 8; w++) s += sh[w][a][b];
        if (s) {
            atomicAdd(&g_h64[a][0][b], s & 0xFFFFFFFFull);  // wc
            atomicAdd(&g_h64[a][1][b], s >> 32);            // wu
        }
    }
    __syncthreads();

    // last-block epilogue
    if (threadIdx.x == 0) {
        __threadfence();
        unsigned done = atomicAdd(&g_done, 1u);
        isLast = (done == gridDim.x - 1);
    }
    __syncthreads();
    if (isLast && threadIdx.x < 32) {
        const double SC = 1.0 / (double)WSCALE;
        double cac = 0, cau = 0, cic = 0, ciu = 0, au_all = 0, iu_all = 0;
        for (int t = 0; t < NTH; t++) {
            double h0 = (double)g_h64[0][0][t] * SC;  // ac
            double h1 = (double)g_h64[0][1][t] * SC;  // au
            double h2 = (double)g_h64[1][0][t] * SC;  // ic
            double h3 = (double)g_h64[1][1][t] * SC;  // iu
            au_all += h1; iu_all += h3;
            if (t <= lane) { cac += h0; cau += h1; cic += h2; ciu += h3; }
        }
        double avu = 0.0;
        if (lane < NTH) {
            double n_au = au_all - cau, n_iu = iu_all - ciu;
            avu = (cac + n_iu) / (cac + n_au + cic + n_iu + EPSV);
        }
        double nxt = __shfl_down_sync(FULL, avu, 1);
        double seg = 0.0;
        if (lane < NTH - 1) {
            float dt = (float)(lane + 1) * 0.05f - (float)lane * 0.05f;
            seg = 0.5 * (avu + nxt) * (double)dt;
        }
        #pragma unroll
        for (int off = 16; off; off >>= 1)
            seg += __shfl_xor_sync(FULL, seg, off);
        if (lane == 0) {
            out[0] = (float)(-log(seg + EPSV));  // avu_loss
            out[1] = (float)seg;                 // auc_avu
        }
        __syncwarp();
        // reset global reduction state for the next graph replay
        for (int t = lane; t < 2 * 2 * NTH; t += 32)
            ((unsigned long long*)g_h64)[t] = 0ull;
        if (lane == 0) {
            g_umin_bits = 0x7f7fffff;
            g_umax_bits = 0;
            g_done = 0u;
        }
    }
}

// ---------------------------------------------------------------------------
extern "C" void kernel_launch(void* const* d_in, const int* in_sizes, int n_in,
                              void* d_out, int out_size) {
    const float* logits = (const float*)d_in[0];
    const int*   labels = (const int*)d_in[1];
    int N = in_sizes[1];  // labels count = rows
    if (N > NMAX) N = NMAX;
    int nSub = (N + SUB_ROWS - 1) / SUB_ROWS;

    static int smemSet = 0;
    if (!smemSet) {
        cudaFuncSetAttribute(k_phase1, cudaFuncAttributeMaxDynamicSharedMemorySize,
                             2 * SUB_F4 * 16);
        smemSet = 1;
    }

    // 296 blocks = 2 resident/SM (2 x 100KB smem), double-buffered pipeline
    k_phase1<<<296, 256, 2 * SUB_F4 * 16>>>(
        (const float4*)logits, labels, N, nSub);
    k_phase2<<<592, 256>>>(N, (float*)d_out);
}

// round 15
// speedup vs baseline: 1.4563x; 1.1036x over previous
#include <cuda_runtime.h>
#include <stdint.h>

// ---------------------------------------------------------------------------
// AUAvULoss. Phase 1: TMA bulk-copy double-buffered tiles (one cp.async.bulk
// per 50KB sub-tile), row-per-thread softmax stats + tanh/weight precompute
// (16-bit fixed point; accurate flag in entropy sign bit).
// Phase 2: match_any+redux aggregated histogram atomics (deterministic int).
// N = 1<<20 rows, C = 100 classes.
// ---------------------------------------------------------------------------

#define NMAX (1 << 20)
#define NTH 21
#define EPSV 1e-10
#define SUB_ROWS 128
#define ROW_F4 25                     // 100 floats = 25 float4 per row
#define SUB_F4 (SUB_ROWS * ROW_F4)    // 3200 float4 = 51,200 B per buffer
#define SUB_BYTES (SUB_F4 * 16)
#define L2E 1.4426950408889634f
#define WSCALE 65535.0f

__device__ float2             g_ec[NMAX];        // {+/-entropy (sign=!acc), wc16|wu16<<16}
__device__ int                g_umin_bits = 0x7f7fffff;
__device__ int                g_umax_bits = 0;
__device__ unsigned long long g_h64[2][2][NTH];  // [acc][wc/wu][bin], zero-init
__device__ unsigned           g_done;            // zero-init

// ---------------------------------------------------------------------------
__device__ __forceinline__ unsigned smem_u32(const void* p) {
    unsigned a;
    asm("{ .reg .u64 t; cvta.to.shared.u64 t, %1; cvt.u32.u64 %0, t; }"
        : "=r"(a) : "l"(p));
    return a;
}
__device__ __forceinline__ void mbar_init(unsigned m, unsigned cnt) {
    asm volatile("mbarrier.init.shared.b64 [%0], %1;" :: "r"(m), "r"(cnt) : "memory");
}
__device__ __forceinline__ void mbar_expect_tx(unsigned m, unsigned bytes) {
    asm volatile("mbarrier.arrive.expect_tx.shared.b64 _, [%0], %1;"
                 :: "r"(m), "r"(bytes) : "memory");
}
__device__ __forceinline__ void mbar_wait(unsigned m, unsigned parity) {
    unsigned done;
    asm volatile(
        "{\n\t.reg .pred p;\n\t"
        "mbarrier.try_wait.parity.acquire.cta.shared::cta.b64 p, [%1], %2;\n\t"
        "selp.b32 %0, 1, 0, p;\n\t}"
        : "=r"(done) : "r"(m), "r"(parity) : "memory");
    if (!done) {
        asm volatile(
            "{\n\t.reg .pred P1;\n\t"
            "WL_%=:\n\t"
            "mbarrier.try_wait.parity.acquire.cta.shared::cta.b64 P1, [%0], %1, 0x989680;\n\t"
            "@P1 bra.uni WD_%=;\n\t"
            "bra.uni WL_%=;\n\t"
            "WD_%=:\n\t}"
            :: "r"(m), "r"(parity) : "memory");
    }
}
__device__ __forceinline__ void bulk_g2s(unsigned dst, const void* src,
                                         unsigned bytes, unsigned mbar) {
    asm volatile(
        "cp.async.bulk.shared::cluster.global.mbarrier::complete_tx::bytes "
        "[%0], [%1], %2, [%3];"
        :: "r"(dst), "l"(src), "r"(bytes), "r"(mbar) : "memory");
}

// ---------------------------------------------------------------------------
// Phase 1: grid-stride over 128-row sub-tiles, 2-buffer TMA-bulk pipeline.
// blockDim=128: every thread owns one row of the current sub-tile.
__global__ void __launch_bounds__(128) k_phase1(
    const float4* __restrict__ l4, const int* __restrict__ labels,
    int N, int nSub)
{
    extern __shared__ char smem[];                 // [0,16): mbar[2]; 1024+: buffers
    float4* sbuf = (float4*)(smem + 1024);
    const unsigned mb0 = smem_u32(smem);
    const unsigned mb1 = mb0 + 8;
    const unsigned sb  = smem_u32(sbuf);
    const int tid = threadIdx.x;
    const float POS = __int_as_float(0x7f800000);

    if (tid == 0) { mbar_init(mb0, 1); mbar_init(mb1, 1); }
    __syncthreads();

    float emin = POS, emax = 0.f;
    int ph[2] = {0, 0};

    // prologue: kick off first sub-tile into buffer 0
    if (blockIdx.x < nSub && tid == 0) {
        int s = blockIdx.x;
        unsigned bytes = (unsigned)min(SUB_BYTES, (N - s * SUB_ROWS) * ROW_F4 * 16);
        mbar_expect_tx(mb0, bytes);
        bulk_g2s(sb, l4 + (size_t)s * SUB_F4, bytes, mb0);
    }

    int buf = 0;
    for (int s = blockIdx.x; s < nSub; s += gridDim.x) {
        int sn = s + gridDim.x;
        if (sn < nSub && tid == 0) {    // prefetch next into other buffer
            unsigned mbn = (buf ^ 1) ? mb1 : mb0;
            unsigned bytes = (unsigned)min(SUB_BYTES, (N - sn * SUB_ROWS) * ROW_F4 * 16);
            mbar_expect_tx(mbn, bytes);
            bulk_g2s(sb + (buf ^ 1) * SUB_BYTES, l4 + (size_t)sn * SUB_F4, bytes, mbn);
        }

        mbar_wait(buf ? mb1 : mb0, ph[buf]);   // current sub-tile ready
        ph[buf] ^= 1;

        int grow = s * SUB_ROWS + tid;
        if (grow < N) {
            const float4* r = sbuf + buf * SUB_F4 + tid * ROW_F4;
            float m0 = -POS, m1 = -POS;
            float S0 = 0.f, S1 = 0.f, U0 = 0.f, U1 = 0.f;
            #pragma unroll
            for (int k = 0; k < ROW_F4; k++) {
                float4 v = r[k];
                float e0 = exp2f(v.x * L2E), e1 = exp2f(v.y * L2E);
                float e2 = exp2f(v.z * L2E), e3 = exp2f(v.w * L2E);
                m0 = fmaxf(m0, fmaxf(v.x, v.y));
                m1 = fmaxf(m1, fmaxf(v.z, v.w));
                S0 += e0 + e1;
                S1 += e2 + e3;
                U0 = fmaf(e0, v.x, fmaf(e1, v.y, U0));
                U1 = fmaf(e2, v.z, fmaf(e3, v.w, U1));
            }
            float m = fmaxf(m0, m1);
            float S = S0 + S1, U = U0 + U1;

            int   lab = labels[grow];
            float xl  = ((const float*)r)[lab];

            float rcpS = __frcp_rn(S);
            float ent  = __logf(S) - U * rcpS;        // entropy (>0)
            float conf = exp2f(m * L2E) * rcpS;       // max prob

            // tanh(ent) = 1 - 2/(e^{2*ent}+1), ent >= 0
            float e2t = exp2f(ent * (2.f * L2E));
            float tu  = 1.f - 2.f * __frcp_rn(e2t + 1.f);

            bool acc = (xl == m);
            float a  = acc ? conf : (1.f - conf);
            unsigned wc = (unsigned)__float2int_rn(a * (1.f - tu) * WSCALE);
            unsigned wu = (unsigned)__float2int_rn(a * tu * WSCALE);

            float es = acc ? ent : __uint_as_float(__float_as_uint(ent) | 0x80000000u);
            g_ec[grow] = make_float2(es, __uint_as_float(wc | (wu << 16)));
            emin = fminf(emin, ent);
            emax = fmaxf(emax, ent);
        }
        __syncthreads();   // all consumers done before this buffer is refilled
        buf ^= 1;
    }

    // block reduce entropy min/max (int-bit ordering valid: entropy > 0)
    __shared__ int smin, smax;
    if (tid == 0) { smin = 0x7f7fffff; smax = 0; }
    __syncthreads();
    if (emin < POS) {
        atomicMin(&smin, __float_as_int(emin));
        atomicMax(&smax, __float_as_int(emax));
    }
    __syncthreads();
    if (tid == 0) {
        atomicMin(&g_umin_bits, smin);
        atomicMax(&g_umax_bits, smax);
    }
}

// ---------------------------------------------------------------------------
// Phase 2: match_any-aggregated warp-private u64 histograms (wc lo32 / wu
// hi32, carry-free), leaders-only ATOMS. Integer global flush; last block
// computes AvU -> trapezoid AUC -> loss and resets global state.
__global__ void __launch_bounds__(256) k_phase2(int N, float* out) {
    const unsigned FULL = 0xFFFFFFFFu;
    const int lane = threadIdx.x & 31;
    const int wid  = threadIdx.x >> 5;
    __shared__ unsigned long long sh[8][2][NTH];   // [warp][acc][bin]
    __shared__ bool isLast;

    for (int t = threadIdx.x; t < 8 * 2 * NTH; t += blockDim.x)
        ((unsigned long long*)sh)[t] = 0ull;
    __syncthreads();

    const float umin  = __int_as_float(g_umin_bits);
    const float range = __int_as_float(g_umax_bits) - umin;
    const float inv   = 20.f / range;

    for (int i = blockIdx.x * blockDim.x + threadIdx.x;
         i < N + blockDim.x * gridDim.x;            // keep warps converged
         i += gridDim.x * blockDim.x) {
        unsigned key = 63u, wc = 0u, wu = 0u;
        if (i < N) {
            float2 ec = g_ec[i];
            unsigned eb = __float_as_uint(ec.x);
            unsigned accIdx = eb >> 31;                    // 0 = accurate
            float ent = __uint_as_float(eb & 0x7FFFFFFFu);

            // bin = #{t : th(t) < ent}; direct estimate + boundary fixup
            int b = (int)((ent - umin) * inv);
            b = max(0, min(20, b));
            float thb = fmaf((float)b * 0.05f, range, umin);
            if (ent > thb) b++;
            else if (b > 0 && ent <= fmaf((float)(b - 1) * 0.05f, range, umin)) b--;
            if (b > 20) b = 20;

            unsigned q = __float_as_uint(ec.y);
            wc = q & 0xFFFFu; wu = q >> 16;
            key = (unsigned)b | (accIdx << 5);
        }
        if (__ballot_sync(FULL, 1) != FULL) {}  // (no-op; all lanes converged)
        unsigned mask = __match_any_sync(FULL, key);
        unsigned wcs = __reduce_add_sync(mask, wc);
        unsigned wus = __reduce_add_sync(mask, wu);
        if (key != 63u && lane == (int)(__ffs(mask) - 1))
            atomicAdd(&sh[wid][key >> 5][key & 31u],
                      ((unsigned long long)wus << 32) | wcs);
    }
    __syncthreads();

    // block-combine 8 warp copies, flush split fields to global (integer)
    for (int t = threadIdx.x; t < 2 * NTH; t += blockDim.x) {
        int a = t / NTH, b = t % NTH;
        unsigned long long s = 0ull;
        #pragma unroll
        for (int w = 0; w < 8; w++) s += sh[w][a][b];
        if (s) {
            atomicAdd(&g_h64[a][0][b], s & 0xFFFFFFFFull);  // wc
            atomicAdd(&g_h64[a][1][b], s >> 32);            // wu
        }
    }
    __syncthreads();

    // last-block epilogue
    if (threadIdx.x == 0) {
        __threadfence();
        unsigned done = atomicAdd(&g_done, 1u);
        isLast = (done == gridDim.x - 1);
    }
    __syncthreads();
    if (isLast && threadIdx.x < 32) {
        const double SC = 1.0 / (double)WSCALE;
        double cac = 0, cau = 0, cic = 0, ciu = 0, au_all = 0, iu_all = 0;
        for (int t = 0; t < NTH; t++) {
            double h0 = (double)g_h64[0][0][t] * SC;  // ac
            double h1 = (double)g_h64[0][1][t] * SC;  // au
            double h2 = (double)g_h64[1][0][t] * SC;  // ic
            double h3 = (double)g_h64[1][1][t] * SC;  // iu
            au_all += h1; iu_all += h3;
            if (t <= lane) { cac += h0; cau += h1; cic += h2; ciu += h3; }
        }
        double avu = 0.0;
        if (lane < NTH) {
            double n_au = au_all - cau, n_iu = iu_all - ciu;
            avu = (cac + n_iu) / (cac + n_au + cic + n_iu + EPSV);
        }
        double nxt = __shfl_down_sync(FULL, avu, 1);
        double seg = 0.0;
        if (lane < NTH - 1) {
            float dt = (float)(lane + 1) * 0.05f - (float)lane * 0.05f;
            seg = 0.5 * (avu + nxt) * (double)dt;
        }
        #pragma unroll
        for (int off = 16; off; off >>= 1)
            seg += __shfl_xor_sync(FULL, seg, off);
        if (lane == 0) {
            out[0] = (float)(-log(seg + EPSV));  // avu_loss
            out[1] = (float)seg;                 // auc_avu
        }
        __syncwarp();
        // reset global reduction state for the next graph replay
        for (int t = lane; t < 2 * 2 * NTH; t += 32)
            ((unsigned long long*)g_h64)[t] = 0ull;
        if (lane == 0) {
            g_umin_bits = 0x7f7fffff;
            g_umax_bits = 0;
            g_done = 0u;
        }
    }
}

// ---------------------------------------------------------------------------
extern "C" void kernel_launch(void* const* d_in, const int* in_sizes, int n_in,
                              void* d_out, int out_size) {
    const float* logits = (const float*)d_in[0];
    const int*   labels = (const int*)d_in[1];
    int N = in_sizes[1];  // labels count = rows
    if (N > NMAX) N = NMAX;
    int nSub = (N + SUB_ROWS - 1) / SUB_ROWS;
    const int smemBytes = 1024 + 2 * SUB_BYTES;   // mbarriers + 2 buffers

    static int smemSet = 0;
    if (!smemSet) {
        cudaFuncSetAttribute(k_phase1, cudaFuncAttributeMaxDynamicSharedMemorySize,
                             smemBytes);
        smemSet = 1;
    }

    // 296 blocks = 2 resident/SM (2 x ~101KB smem), TMA double-buffer pipeline
    k_phase1<<<296, 128, smemBytes>>>((const float4*)logits, labels, N, nSub);
    k_phase2<<<592, 256>>>(N, (float*)d_out);
}